// round 12
// baseline (speedup 1.0000x reference)
#include <cuda_runtime.h>
#include <cstdint>

#define NT 256
#define ROWP 72
#define SEG  4608          // 64 * ROWP

// Dynamic pool offsets (floats)
#define OFF_U    0         // U (B) / GB cols 0-63 (E)
#define OFF_H1A  4608      // H1a (B) / SIG (D) / GB 64-127 (E)
#define OFF_H1B  9216      // H1b (B) / selfH1 scratch (C) / GB 128-191 (E)
#define OFF_MN   13824     // MN (B..D) / RES (D..E, in place)
#define OFF_HT   18432     // raw ht (persistent)
#define OFF_WF   23040     // weight staging (4096, single buffer)
#define SMEM_FLOATS 27136  // 108544 bytes dynamic

__device__ float g_adj[2048];
__device__ float g_P1[2 * 1024 * 64];

static __device__ __forceinline__ float clipf(float x, float lo, float hi) {
    return fminf(fmaxf(x, lo), hi);
}
static __device__ __forceinline__ float sigf(float x) {
    return 1.0f / (1.0f + expf(-x));
}
static __device__ __forceinline__ unsigned f2tf(float x) {
    unsigned r;
    asm("cvt.rna.tf32.f32 %0, %1;" : "=r"(r) : "f"(x));
    return r;
}
static __device__ __forceinline__ void mma_tf32(float d[4],
                                                unsigned a0, unsigned a1,
                                                unsigned a2, unsigned a3,
                                                unsigned b0, unsigned b1) {
    asm volatile(
        "mma.sync.aligned.m16n8k8.row.col.f32.tf32.tf32.f32 "
        "{%0,%1,%2,%3}, {%4,%5,%6,%7}, {%8,%9}, {%0,%1,%2,%3};"
        : "+f"(d[0]), "+f"(d[1]), "+f"(d[2]), "+f"(d[3])
        : "r"(a0), "r"(a1), "r"(a2), "r"(a3), "r"(b0), "r"(b1));
}

// ---------------------------------------------------------------------------
// adj: grid (2,8), block 128
// ---------------------------------------------------------------------------
__global__ void adj_kernel(const int* __restrict__ qt,
                           const float* __restrict__ one_hot,
                           const float* __restrict__ graphs)
{
    __shared__ int nzIdx[1024];
    __shared__ int nzCnt;
    const int k = blockIdx.x;
    const int d = blockIdx.y * 128 + threadIdx.x;
    const int tid = threadIdx.x;
    if (tid == 0) nzCnt = 0;
    __syncthreads();
    const int q0 = __ldg(&qt[0]);
    for (int c = tid; c < 1024; c += 128) {
        if (__ldg(&one_hot[(size_t)q0 * 1024 + c]) > 0.5f) {
            int p = atomicAdd(&nzCnt, 1);
            nzIdx[p] = c;
        }
    }
    __syncthreads();
    const int cnt = nzCnt;
    const float denom = fmaxf((float)cnt, 1.0f);
    float s = 0.0f;
    for (int t = 0; t < cnt; ++t)
        s += __ldg(&graphs[((size_t)k * 1024 + (size_t)nzIdx[t]) * 1024 + d]);
    g_adj[k * 1024 + d] = clipf(s / denom, -5.0f, 5.0f);
}

// ---------------------------------------------------------------------------
// P1[k][c][j] = bn1[k][j] + sum_e clip(kcE[c][e],±5) * Wn1[k][192+e][j]
// grid (256, 2), block 256 (4 c's per block share the Wn1 slice via L1)
// ---------------------------------------------------------------------------
__global__ void p1_kernel(const float* __restrict__ kcE,
                          const float* __restrict__ Wn1,
                          const float* __restrict__ bn1)
{
    __shared__ float kcS[4][64];
    const int k = blockIdx.y;
    const int cl = threadIdx.x >> 6;
    const int j  = threadIdx.x & 63;
    const int c  = blockIdx.x * 4 + cl;
    kcS[cl][j] = clipf(__ldg(&kcE[c * 64 + j]), -5.0f, 5.0f);
    __syncthreads();
    float s = __ldg(&bn1[k * 64 + j]);
#pragma unroll 4
    for (int e = 0; e < 64; ++e)
        s = fmaf(kcS[cl][e], __ldg(&Wn1[(size_t)k * 16384 + (size_t)(192 + e) * 64 + j]), s);
    g_P1[((size_t)k * 1024 + c) * 64 + j] = s;
}

// ---------------------------------------------------------------------------
// Weight prefetch (float4 regs) / store (frag order, tf32)
// ---------------------------------------------------------------------------
static __device__ __forceinline__ void wload4(const float* __restrict__ g,
                                              int pitch, int tid, float4 pw[4])
{
#pragma unroll
    for (int q = 0; q < 4; ++q) {
        const int i4 = tid + q * NT;
        const int k = i4 >> 4, j4 = i4 & 15;
        pw[q] = __ldg(reinterpret_cast<const float4*>(g + (size_t)k * pitch) + j4);
    }
}
static __device__ __forceinline__ void wstore4(const float4 pw[4],
                                               float* __restrict__ Wf, int tid)
{
#pragma unroll
    for (int q = 0; q < 4; ++q) {
        const int i4 = tid + q * NT;
        const int k = i4 >> 4, j4 = i4 & 15;
        const int kc = k >> 3, kk = k & 7;
        const int h = kk >> 2, t = kk & 3;
        const float v[4] = {pw[q].x, pw[q].y, pw[q].z, pw[q].w};
#pragma unroll
        for (int e = 0; e < 4; ++e) {
            const int j = j4 * 4 + e;
            const int nc = j >> 3, gg = j & 7;
            Wf[(kc * 8 + nc) * 64 + (gg * 4 + t) * 2 + h] = __uint_as_float(f2tf(v[e]));
        }
    }
}

// A fragments: 16 rows x K=64, converted once, reused across stages.
static __device__ __forceinline__ void load_af(const float* __restrict__ A,
                                               int m0, int t4, int g8,
                                               unsigned af[8][4])
{
    const float* Ab = A + m0 + g8;
#pragma unroll
    for (int kc = 0; kc < 8; ++kc) {
        const float* Ak = Ab + (kc * 8 + t4) * ROWP;
        af[kc][0] = f2tf(Ak[0]);
        af[kc][1] = f2tf(Ak[8]);
        af[kc][2] = f2tf(Ak[4 * ROWP]);
        af[kc][3] = f2tf(Ak[4 * ROWP + 8]);
    }
}
static __device__ __forceinline__ void gemm_frag(const unsigned af[8][4],
                                                 const float* __restrict__ Wf,
                                                 int wn, int lane, float acc[4][4])
{
#pragma unroll
    for (int kc = 0; kc < 8; ++kc) {
#pragma unroll
        for (int c4 = 0; c4 < 4; ++c4) {
            const float2 b = *reinterpret_cast<const float2*>(
                Wf + (kc * 8 + wn * 4 + c4) * 64 + lane * 2);
            mma_tf32(acc[c4], af[kc][0], af[kc][1], af[kc][2], af[kc][3],
                     __float_as_uint(b.x), __float_as_uint(b.y));
        }
    }
}
static __device__ __forceinline__ void zacc(float acc[4][4]) {
#pragma unroll
    for (int i = 0; i < 4; ++i)
#pragma unroll
        for (int j = 0; j < 4; ++j) acc[i][j] = 0.0f;
}

// ---------------------------------------------------------------------------
// Main fused kernel: one block per (b, 64-row c-tile). 256 threads, 8 warps.
// 2 blocks per SM -> overlapping barrier domains.
// ---------------------------------------------------------------------------
extern __shared__ float dynsmem[];

__global__ void __launch_bounds__(NT, 2)
main_kernel(const int*   __restrict__ qt,
            const float* __restrict__ ht,
            const float* __restrict__ one_hot,
            const float* __restrict__ kcE,
            const float* __restrict__ nwp,
            const float* __restrict__ Ws1, const float* __restrict__ bs1,
            const float* __restrict__ Ws2, const float* __restrict__ bs2,
            const float* __restrict__ Wn1, const float* __restrict__ bn1,
            const float* __restrict__ Wn2, const float* __restrict__ bn2,
            const float* __restrict__ ea_w,
            const float* __restrict__ We,  const float* __restrict__ be,
            const float* __restrict__ Wa,  const float* __restrict__ ba,
            const float* __restrict__ W_ih, const float* __restrict__ b_ih,
            const float* __restrict__ W_hh, const float* __restrict__ b_hh,
            const float* __restrict__ Wpv, const float* __restrict__ bp,
            float* __restrict__ out)
{
    const int tid  = threadIdx.x;
    const int lane = tid & 31;
    const int warpId = tid >> 5;
    const int wm = warpId & 3;
    const int wn = warpId >> 2;
    const int m0 = wm * 16;
    const int t4 = lane & 3;
    const int g8 = lane >> 2;
    const int rA = m0 + g8;
    const int rB = rA + 8;
    const int c0 = blockIdx.x * 64;
    const int b  = blockIdx.y;

    float* pool = dynsmem;
    float* U   = pool + OFF_U;
    float* H1A = pool + OFF_H1A;   // SIG in D
    float* H1B = pool + OFF_H1B;   // selfH1 scratch in C
    float* MN  = pool + OFF_MN;    // RES in D..E
    float* HT  = pool + OFF_HT;
    float* GB  = pool + OFF_U;     // 192 x ROWP in phase E
    float* Wf  = pool + OFF_WF;

    __shared__ float adj0S[64], adj1S[64], eaS[64], WpS[64];
    __shared__ float yS2[128];
    __shared__ int selfRows[64];
    __shared__ int selfCnt;

    if (tid == 0) selfCnt = 0;
    __syncthreads();

    float4 pw[4];
    unsigned af[8][4];
    float acc[4][4];

    // ---------------- Phase A: prefetch S0 weights + metadata + HT/U ----------
    wload4(Wn1 + 128 * 64, 64, tid, pw);           // S0 = Wn1[0] rows 128..191

    const int qb = __ldg(&qt[b]);
    if (tid < 64) {
        const int row = tid;
        const int c = c0 + row;
        const float m = __ldg(&one_hot[(size_t)qb * 1024 + c]);
        adj0S[row] = g_adj[c];
        adj1S[row] = g_adj[1024 + c];
        eaS[row]   = __ldg(&ea_w[c]);
        WpS[row]   = __ldg(&Wpv[row]);
        if (m > 0.5f) { int p = atomicAdd(&selfCnt, 1); selfRows[p] = row; }
    }

    for (int i = tid; i < 1024; i += NT) {
        const int row = i & 63;
        const int f4  = i >> 6;
        const float4 v = __ldg(reinterpret_cast<const float4*>(
                               &ht[((size_t)b * 1024 + c0 + row) * 64]) + f4);
        const int f = f4 * 4;
        HT[(f + 0) * ROWP + row] = v.x;
        HT[(f + 1) * ROWP + row] = v.y;
        HT[(f + 2) * ROWP + row] = v.z;
        HT[(f + 3) * ROWP + row] = v.w;
        U[(f + 0) * ROWP + row] = clipf(v.x, -5.0f, 5.0f);
        U[(f + 1) * ROWP + row] = clipf(v.y, -5.0f, 5.0f);
        U[(f + 2) * ROWP + row] = clipf(v.z, -5.0f, 5.0f);
        U[(f + 3) * ROWP + row] = clipf(v.w, -5.0f, 5.0f);
    }
    __syncthreads();
    wstore4(pw, Wf, tid);
    __syncthreads();

    const float w = clipf(__ldg(&nwp[0]), 0.1f, 0.9f);

    // ---------------- S0: U @ Wn1[0] -> H1A -----------------------------------
    wload4(Wn1 + 16384 + 128 * 64, 64, tid, pw);   // S1
    load_af(U, m0, t4, g8, af);
    zacc(acc);
    gemm_frag(af, Wf, wn, lane, acc);
    {
        const float* P1k = g_P1;
#pragma unroll
        for (int c4 = 0; c4 < 4; ++c4) {
            const int j0 = (wn * 4 + c4) * 8 + 2 * t4;
            const float2 pa = *reinterpret_cast<const float2*>(&P1k[(size_t)(c0 + rA) * 64 + j0]);
            const float2 pb = *reinterpret_cast<const float2*>(&P1k[(size_t)(c0 + rB) * 64 + j0]);
            H1A[j0 * ROWP + rA]       = fmaxf(acc[c4][0] + pa.x, 0.0f);
            H1A[(j0 + 1) * ROWP + rA] = fmaxf(acc[c4][1] + pa.y, 0.0f);
            H1A[j0 * ROWP + rB]       = fmaxf(acc[c4][2] + pb.x, 0.0f);
            H1A[(j0 + 1) * ROWP + rB] = fmaxf(acc[c4][3] + pb.y, 0.0f);
        }
    }
    __syncthreads();
    wstore4(pw, Wf, tid);
    __syncthreads();

    // ---------------- S1: U @ Wn1[1] -> H1B (af reuse) ------------------------
    wload4(Wn2, 64, tid, pw);                      // S2
    zacc(acc);
    gemm_frag(af, Wf, wn, lane, acc);
    {
        const float* P1k = g_P1 + (size_t)1024 * 64;
#pragma unroll
        for (int c4 = 0; c4 < 4; ++c4) {
            const int j0 = (wn * 4 + c4) * 8 + 2 * t4;
            const float2 pa = *reinterpret_cast<const float2*>(&P1k[(size_t)(c0 + rA) * 64 + j0]);
            const float2 pb = *reinterpret_cast<const float2*>(&P1k[(size_t)(c0 + rB) * 64 + j0]);
            H1B[j0 * ROWP + rA]       = fmaxf(acc[c4][0] + pa.x, 0.0f);
            H1B[(j0 + 1) * ROWP + rA] = fmaxf(acc[c4][1] + pa.y, 0.0f);
            H1B[j0 * ROWP + rB]       = fmaxf(acc[c4][2] + pb.x, 0.0f);
            H1B[(j0 + 1) * ROWP + rB] = fmaxf(acc[c4][3] + pb.y, 0.0f);
        }
    }
    __syncthreads();
    wstore4(pw, Wf, tid);
    __syncthreads();

    // ---------------- S2: H1A @ Wn2[0] -> MN (k=0) ----------------------------
    wload4(Wn2 + 4096, 64, tid, pw);               // S3
    load_af(H1A, m0, t4, g8, af);
    zacc(acc);
    gemm_frag(af, Wf, wn, lane, acc);
#pragma unroll
    for (int c4 = 0; c4 < 4; ++c4) {
        const int j0 = (wn * 4 + c4) * 8 + 2 * t4;
#pragma unroll
        for (int h = 0; h < 2; ++h) {
            const int j = j0 + h;
            const float bb = __ldg(&bn2[j]);
            const float nbA = fminf(fmaxf(acc[c4][h] + bb, 0.0f), 5.0f);
            const float nbB = fminf(fmaxf(acc[c4][2 + h] + bb, 0.0f), 5.0f);
            MN[j * ROWP + rA] = clipf(adj0S[rA] * nbA, -5.0f, 5.0f);
            MN[j * ROWP + rB] = clipf(adj0S[rB] * nbB, -5.0f, 5.0f);
        }
    }
    __syncthreads();
    wstore4(pw, Wf, tid);
    __syncthreads();

    // ---------------- S3: H1B @ Wn2[1] -> MN combine --------------------------
    wload4(We, 64, tid, pw);                       // S4
    load_af(H1B, m0, t4, g8, af);
    zacc(acc);
    gemm_frag(af, Wf, wn, lane, acc);
#pragma unroll
    for (int c4 = 0; c4 < 4; ++c4) {
        const int j0 = (wn * 4 + c4) * 8 + 2 * t4;
#pragma unroll
        for (int h = 0; h < 2; ++h) {
            const int j = j0 + h;
            const float bb = __ldg(&bn2[64 + j]);
            const float nbA = fminf(fmaxf(acc[c4][h] + bb, 0.0f), 5.0f);
            const float nbB = fminf(fmaxf(acc[c4][2 + h] + bb, 0.0f), 5.0f);
            float* mA = &MN[j * ROWP + rA];
            float* mB = &MN[j * ROWP + rB];
            *mA = clipf(w * (*mA) + (1.0f - w) * adj1S[rA] * nbA, -5.0f, 5.0f);
            *mB = clipf(w * (*mB) + (1.0f - w) * adj1S[rB] * nbB, -5.0f, 5.0f);
        }
    }
    __syncthreads();

    // ---------------- Phase C: sparse self-MLP fixup --------------------------
    {
        float* selfH1 = H1B;   // dead after S3's af load
        const int nSelf = selfCnt;
        for (int s = warpId; s < nSelf; s += 8) {
            const int row = selfRows[s];
            const int c = c0 + row;
            float a1 = __ldg(&bs1[lane]);
            float a2 = __ldg(&bs1[lane + 32]);
#pragma unroll 4
            for (int i = 0; i < 64; ++i) {
                const float xi = HT[i * ROWP + row];
                a1 = fmaf(xi, __ldg(&Ws1[i * 64 + lane]), a1);
                a2 = fmaf(xi, __ldg(&Ws1[i * 64 + lane + 32]), a2);
            }
#pragma unroll 4
            for (int i = 0; i < 64; ++i) {
                const float xi = __ldg(&kcE[(size_t)c * 64 + i]);
                a1 = fmaf(xi, __ldg(&Ws1[(64 + i) * 64 + lane]), a1);
                a2 = fmaf(xi, __ldg(&Ws1[(64 + i) * 64 + lane + 32]), a2);
            }
            selfH1[warpId * 64 + lane]      = fmaxf(a1, 0.0f);
            selfH1[warpId * 64 + lane + 32] = fmaxf(a2, 0.0f);
            __syncwarp();
            float o1 = __ldg(&bs2[lane]);
            float o2 = __ldg(&bs2[lane + 32]);
#pragma unroll 4
            for (int i = 0; i < 64; ++i) {
                const float h = selfH1[warpId * 64 + i];
                o1 = fmaf(h, __ldg(&Ws2[i * 64 + lane]), o1);
                o2 = fmaf(h, __ldg(&Ws2[i * 64 + lane + 32]), o2);
            }
            MN[lane * ROWP + row]        = fminf(fmaxf(o1, 0.0f), 10.0f);
            MN[(lane + 32) * ROWP + row] = fminf(fmaxf(o2, 0.0f), 10.0f);
            __syncwarp();
        }
    }
    __syncthreads();
    wstore4(pw, Wf, tid);                          // S4 weights
    __syncthreads();

    // ---------------- S4: MN @ We -> SIG --------------------------------------
    float* SIG = H1A;
    float* RES = MN;

    wload4(Wa, 64, tid, pw);                       // S5
    load_af(MN, m0, t4, g8, af);
    zacc(acc);
    gemm_frag(af, Wf, wn, lane, acc);
#pragma unroll
    for (int c4 = 0; c4 < 4; ++c4) {
        const int j0 = (wn * 4 + c4) * 8 + 2 * t4;
#pragma unroll
        for (int h = 0; h < 2; ++h) {
            const int j = j0 + h;
            const float bb = __ldg(&be[j]);
            SIG[j * ROWP + rA] = sigf(acc[c4][h] + bb);
            SIG[j * ROWP + rB] = sigf(acc[c4][2 + h] + bb);
        }
    }
    __syncthreads();
    wstore4(pw, Wf, tid);
    __syncthreads();

    // ---------------- S5: MN @ Wa -> RES (in place, af reuse) -----------------
    wload4(W_hh, 192, tid, pw);                    // S6
    zacc(acc);
    gemm_frag(af, Wf, wn, lane, acc);
#pragma unroll
    for (int c4 = 0; c4 < 4; ++c4) {
        const int j0 = (wn * 4 + c4) * 8 + 2 * t4;
#pragma unroll
        for (int h = 0; h < 2; ++h) {
            const int j = j0 + h;
            const float bb = __ldg(&ba[j]);
            {
                const float mn = MN[j * ROWP + rA];
                const float g  = eaS[rA];
                RES[j * ROWP + rA] = mn - g * SIG[j * ROWP + rA] * mn + g * tanhf(acc[c4][h] + bb);
            }
            {
                const float mn = MN[j * ROWP + rB];
                const float g  = eaS[rB];
                RES[j * ROWP + rB] = mn - g * SIG[j * ROWP + rB] * mn + g * tanhf(acc[c4][2 + h] + bb);
            }
        }
    }
    __syncthreads();
    wstore4(pw, Wf, tid);
    __syncthreads();

    // ---------------- S6..S8: HT @ W_hh -> GB (af loaded once) ----------------
    load_af(HT, m0, t4, g8, af);
#pragma unroll 1
    for (int p = 0; p < 3; ++p) {
        if (p == 0)      wload4(W_hh + 64, 192, tid, pw);
        else if (p == 1) wload4(W_hh + 128, 192, tid, pw);
        else             wload4(W_ih, 192, tid, pw);
        zacc(acc);
        gemm_frag(af, Wf, wn, lane, acc);
#pragma unroll
        for (int c4 = 0; c4 < 4; ++c4) {
            const int j0 = (wn * 4 + c4) * 8 + 2 * t4;
#pragma unroll
            for (int h = 0; h < 2; ++h) {
                const int j = p * 64 + j0 + h;
                const float bb = __ldg(&b_hh[j]);
                GB[j * ROWP + rA] = acc[c4][h] + bb;
                GB[j * ROWP + rB] = acc[c4][2 + h] + bb;
            }
        }
        __syncthreads();
        wstore4(pw, Wf, tid);
        __syncthreads();
    }

    // ---------------- S9..S10: RES @ W_ih -> gates (af loaded once) -----------
    load_af(RES, m0, t4, g8, af);
#pragma unroll 1
    for (int p = 0; p < 2; ++p) {
        if (p == 0) wload4(W_ih + 64, 192, tid, pw);
        else        wload4(W_ih + 128, 192, tid, pw);
        zacc(acc);
        gemm_frag(af, Wf, wn, lane, acc);
#pragma unroll
        for (int c4 = 0; c4 < 4; ++c4) {
            const int j0 = (wn * 4 + c4) * 8 + 2 * t4;
#pragma unroll
            for (int h = 0; h < 2; ++h) {
                const int j = p * 64 + j0 + h;
                const float bb = __ldg(&b_ih[j]);
                GB[j * ROWP + rA] = sigf(acc[c4][h] + bb + GB[j * ROWP + rA]);
                GB[j * ROWP + rB] = sigf(acc[c4][2 + h] + bb + GB[j * ROWP + rB]);
            }
        }
        __syncthreads();
        wstore4(pw, Wf, tid);
        __syncthreads();
    }

    // ---------------- S11: final gi pass + GRU + readout ----------------------
    zacc(acc);
    gemm_frag(af, Wf, wn, lane, acc);
    {
        float ypA = 0.0f, ypB = 0.0f;
#pragma unroll
        for (int c4 = 0; c4 < 4; ++c4) {
            const int j0 = (wn * 4 + c4) * 8 + 2 * t4;
#pragma unroll
            for (int h = 0; h < 2; ++h) {
                const int j = j0 + h;
                const float bb = __ldg(&b_ih[128 + j]);
                const float wp = WpS[j];
                {
                    const float r  = GB[j * ROWP + rA];
                    const float z  = GB[(64 + j) * ROWP + rA];
                    const float hn = GB[(128 + j) * ROWP + rA];
                    const float n  = tanhf(acc[c4][h] + bb + r * hn);
                    const float hv = HT[j * ROWP + rA];
                    ypA += ((1.0f - z) * n + z * hv) * wp;
                }
                {
                    const float r  = GB[j * ROWP + rB];
                    const float z  = GB[(64 + j) * ROWP + rB];
                    const float hn = GB[(128 + j) * ROWP + rB];
                    const float n  = tanhf(acc[c4][2 + h] + bb + r * hn);
                    const float hv = HT[j * ROWP + rB];
                    ypB += ((1.0f - z) * n + z * hv) * wp;
                }
            }
        }
        ypA += __shfl_xor_sync(0xffffffffu, ypA, 1);
        ypA += __shfl_xor_sync(0xffffffffu, ypA, 2);
        ypB += __shfl_xor_sync(0xffffffffu, ypB, 1);
        ypB += __shfl_xor_sync(0xffffffffu, ypB, 2);
        if (t4 == 0) {
            yS2[wn * 64 + rA] = ypA;
            yS2[wn * 64 + rB] = ypB;
        }
    }
    __syncthreads();

    if (tid < 64) {
        out[(size_t)b * 1024 + c0 + tid] =
            sigf(yS2[tid] + yS2[64 + tid] + __ldg(&bp[0]));
    }
}

// ---------------------------------------------------------------------------
// Launcher
// ---------------------------------------------------------------------------
extern "C" void kernel_launch(void* const* d_in, const int* in_sizes, int n_in,
                              void* d_out, int out_size)
{
    const int*   qt     = (const int*)  d_in[1];
    const float* ht     = (const float*)d_in[2];
    const float* oh     = (const float*)d_in[3];
    const float* kcE    = (const float*)d_in[4];
    const float* graphs = (const float*)d_in[5];
    const float* nw     = (const float*)d_in[6];
    const float* Ws1    = (const float*)d_in[7];
    const float* bs1    = (const float*)d_in[8];
    const float* Ws2    = (const float*)d_in[9];
    const float* bs2    = (const float*)d_in[10];
    const float* Wn1    = (const float*)d_in[11];
    const float* bn1    = (const float*)d_in[12];
    const float* Wn2    = (const float*)d_in[13];
    const float* bn2    = (const float*)d_in[14];
    const float* ea     = (const float*)d_in[15];
    const float* We     = (const float*)d_in[16];
    const float* be     = (const float*)d_in[17];
    const float* Wa     = (const float*)d_in[18];
    const float* ba     = (const float*)d_in[19];
    const float* Wih    = (const float*)d_in[20];
    const float* bih    = (const float*)d_in[21];
    const float* Whh    = (const float*)d_in[22];
    const float* bhh    = (const float*)d_in[23];
    const float* Wp     = (const float*)d_in[24];
    const float* bp     = (const float*)d_in[25];
    float* out = (float*)d_out;

    adj_kernel<<<dim3(2, 8), 128>>>(qt, oh, graphs);
    p1_kernel<<<dim3(256, 2), 256>>>(kcE, Wn1, bn1);

    const int smemBytes = SMEM_FLOATS * (int)sizeof(float); // 108544
    cudaFuncSetAttribute(main_kernel,
                         cudaFuncAttributeMaxDynamicSharedMemorySize, smemBytes);

    dim3 grid(16, 256);
    main_kernel<<<grid, NT, smemBytes>>>(qt, ht, oh, kcE, nw,
                                         Ws1, bs1, Ws2, bs2,
                                         Wn1, bn1, Wn2, bn2,
                                         ea, We, be, Wa, ba,
                                         Wih, bih, Whh, bhh, Wp, bp, out);
}

// round 13
// speedup vs baseline: 1.2213x; 1.2213x over previous
#include <cuda_runtime.h>
#include <cstdint>

#define NT 512
#define ROWP 136
#define SEG  8704          // 64 * ROWP

// Dynamic pool offsets (floats)
#define OFF_H1A  0         // H1a (Sec1-2) / SIG (Sec3) / iz,z (Sec4-6)
#define OFF_H1B  8704      // H1b (Sec1-2) / fixup scratch / RES (Sec3-5) / in_ (Sec5-6)
#define OFF_MN   17408     // MN (Sec2-3) / ir,r (Sec4-6)
#define OFF_HT   26112     // raw ht (persistent)
#define OFF_WB   34816     // 4 x 4096 weight ring
#define SMEM_FLOATS 51200  // 204800 bytes dynamic

__device__ float g_adj[2048];
__device__ float g_P1[2 * 1024 * 64];

static __device__ __forceinline__ float clipf(float x, float lo, float hi) {
    return fminf(fmaxf(x, lo), hi);
}
static __device__ __forceinline__ float sigf(float x) {
    return 1.0f / (1.0f + expf(-x));
}
static __device__ __forceinline__ unsigned f2tf(float x) {
    unsigned r;
    asm("cvt.rna.tf32.f32 %0, %1;" : "=r"(r) : "f"(x));
    return r;
}
static __device__ __forceinline__ void mma_tf32(float d[4],
                                                unsigned a0, unsigned a1,
                                                unsigned a2, unsigned a3,
                                                unsigned b0, unsigned b1) {
    asm volatile(
        "mma.sync.aligned.m16n8k8.row.col.f32.tf32.tf32.f32 "
        "{%0,%1,%2,%3}, {%4,%5,%6,%7}, {%8,%9}, {%0,%1,%2,%3};"
        : "+f"(d[0]), "+f"(d[1]), "+f"(d[2]), "+f"(d[3])
        : "r"(a0), "r"(a1), "r"(a2), "r"(a3), "r"(b0), "r"(b1));
}

// ---------------------------------------------------------------------------
// adj: grid (2,8), block 128
// ---------------------------------------------------------------------------
__global__ void adj_kernel(const int* __restrict__ qt,
                           const float* __restrict__ one_hot,
                           const float* __restrict__ graphs)
{
    __shared__ int nzIdx[1024];
    __shared__ int nzCnt;
    const int k = blockIdx.x;
    const int d = blockIdx.y * 128 + threadIdx.x;
    const int tid = threadIdx.x;
    if (tid == 0) nzCnt = 0;
    __syncthreads();
    const int q0 = __ldg(&qt[0]);
    for (int c = tid; c < 1024; c += 128) {
        if (__ldg(&one_hot[(size_t)q0 * 1024 + c]) > 0.5f) {
            int p = atomicAdd(&nzCnt, 1);
            nzIdx[p] = c;
        }
    }
    __syncthreads();
    const int cnt = nzCnt;
    const float denom = fmaxf((float)cnt, 1.0f);
    float s = 0.0f;
    for (int t = 0; t < cnt; ++t)
        s += __ldg(&graphs[((size_t)k * 1024 + (size_t)nzIdx[t]) * 1024 + d]);
    g_adj[k * 1024 + d] = clipf(s / denom, -5.0f, 5.0f);
}

// ---------------------------------------------------------------------------
// P1[k][c][j] = bn1[k][j] + sum_e clip(kcE[c][e],±5) * Wn1[k][192+e][j]
// ---------------------------------------------------------------------------
__global__ void p1_kernel(const float* __restrict__ kcE,
                          const float* __restrict__ Wn1,
                          const float* __restrict__ bn1)
{
    __shared__ float kcS[4][64];
    const int k = blockIdx.y;
    const int cl = threadIdx.x >> 6;
    const int j  = threadIdx.x & 63;
    const int c  = blockIdx.x * 4 + cl;
    kcS[cl][j] = clipf(__ldg(&kcE[c * 64 + j]), -5.0f, 5.0f);
    __syncthreads();
    float s = __ldg(&bn1[k * 64 + j]);
#pragma unroll 4
    for (int e = 0; e < 64; ++e)
        s = fmaf(kcS[cl][e], __ldg(&Wn1[(size_t)k * 16384 + (size_t)(192 + e) * 64 + j]), s);
    g_P1[((size_t)k * 1024 + c) * 64 + j] = s;
}

// ---------------------------------------------------------------------------
// Weight prefetch (2x float4 regs) / store (frag order, tf32)
// ---------------------------------------------------------------------------
static __device__ __forceinline__ void wload2(const float* __restrict__ g,
                                              int pitch, int tid, float4 pw[2])
{
#pragma unroll
    for (int q = 0; q < 2; ++q) {
        const int i4 = tid + q * NT;
        const int k = i4 >> 4, j4 = i4 & 15;
        pw[q] = __ldg(reinterpret_cast<const float4*>(g + (size_t)k * pitch) + j4);
    }
}
static __device__ __forceinline__ void wstore2(const float4 pw[2],
                                               float* __restrict__ Wf, int tid)
{
#pragma unroll
    for (int q = 0; q < 2; ++q) {
        const int i4 = tid + q * NT;
        const int k = i4 >> 4, j4 = i4 & 15;
        const int kc = k >> 3, kk = k & 7;
        const int h = kk >> 2, t = kk & 3;
        const float v[4] = {pw[q].x, pw[q].y, pw[q].z, pw[q].w};
#pragma unroll
        for (int e = 0; e < 4; ++e) {
            const int j = j4 * 4 + e;
            const int nc = j >> 3, gg = j & 7;
            Wf[(kc * 8 + nc) * 64 + (gg * 4 + t) * 2 + h] = __uint_as_float(f2tf(v[e]));
        }
    }
}

// A fragments: 16 rows x K=64, converted once, reused across stages.
static __device__ __forceinline__ void load_af(const float* __restrict__ A,
                                               int m0, int t4, int g8,
                                               unsigned af[8][4])
{
    const float* Ab = A + m0 + g8;
#pragma unroll
    for (int kc = 0; kc < 8; ++kc) {
        const float* Ak = Ab + (kc * 8 + t4) * ROWP;
        af[kc][0] = f2tf(Ak[0]);
        af[kc][1] = f2tf(Ak[8]);
        af[kc][2] = f2tf(Ak[4 * ROWP]);
        af[kc][3] = f2tf(Ak[4 * ROWP + 8]);
    }
}
// clip applied on the fly (U buffer eliminated)
static __device__ __forceinline__ void load_af_clip(const float* __restrict__ A,
                                                    int m0, int t4, int g8,
                                                    unsigned af[8][4])
{
    const float* Ab = A + m0 + g8;
#pragma unroll
    for (int kc = 0; kc < 8; ++kc) {
        const float* Ak = Ab + (kc * 8 + t4) * ROWP;
        af[kc][0] = f2tf(clipf(Ak[0], -5.0f, 5.0f));
        af[kc][1] = f2tf(clipf(Ak[8], -5.0f, 5.0f));
        af[kc][2] = f2tf(clipf(Ak[4 * ROWP], -5.0f, 5.0f));
        af[kc][3] = f2tf(clipf(Ak[4 * ROWP + 8], -5.0f, 5.0f));
    }
}
static __device__ __forceinline__ void gemm_frag(const unsigned af[8][4],
                                                 const float* __restrict__ Wf,
                                                 int wn, int lane, float acc[4][4])
{
#pragma unroll
    for (int kc = 0; kc < 8; ++kc) {
#pragma unroll
        for (int c4 = 0; c4 < 4; ++c4) {
            const float2 b = *reinterpret_cast<const float2*>(
                Wf + (kc * 8 + wn * 4 + c4) * 64 + lane * 2);
            mma_tf32(acc[c4], af[kc][0], af[kc][1], af[kc][2], af[kc][3],
                     __float_as_uint(b.x), __float_as_uint(b.y));
        }
    }
}
static __device__ __forceinline__ void zacc(float acc[4][4]) {
#pragma unroll
    for (int i = 0; i < 4; ++i)
#pragma unroll
        for (int j = 0; j < 4; ++j) acc[i][j] = 0.0f;
}

// ---------------------------------------------------------------------------
// Main fused kernel: one block per (b, 128-row c-tile). 512 threads, 16 warps.
// 6 two-GEMM sections, 8 barriers total.
// ---------------------------------------------------------------------------
extern __shared__ float dynsmem[];

__global__ void __launch_bounds__(NT, 1)
main_kernel(const int*   __restrict__ qt,
            const float* __restrict__ ht,
            const float* __restrict__ one_hot,
            const float* __restrict__ kcE,
            const float* __restrict__ nwp,
            const float* __restrict__ Ws1, const float* __restrict__ bs1,
            const float* __restrict__ Ws2, const float* __restrict__ bs2,
            const float* __restrict__ Wn1, const float* __restrict__ bn1,
            const float* __restrict__ Wn2, const float* __restrict__ bn2,
            const float* __restrict__ ea_w,
            const float* __restrict__ We,  const float* __restrict__ be,
            const float* __restrict__ Wa,  const float* __restrict__ ba,
            const float* __restrict__ W_ih, const float* __restrict__ b_ih,
            const float* __restrict__ W_hh, const float* __restrict__ b_hh,
            const float* __restrict__ Wpv, const float* __restrict__ bp,
            float* __restrict__ out)
{
    const int tid  = threadIdx.x;
    const int lane = tid & 31;
    const int warpId = tid >> 5;
    const int wm = warpId & 7;
    const int wn = warpId >> 3;
    const int m0 = wm * 16;
    const int t4 = lane & 3;
    const int g8 = lane >> 2;
    const int rA = m0 + g8;
    const int rB = rA + 8;
    const int c0 = blockIdx.x * 128;
    const int b  = blockIdx.y;

    float* pool = dynsmem;
    float* H1A = pool + OFF_H1A;   // SIG / iz,z
    float* H1B = pool + OFF_H1B;   // fixup scratch / RES / in_
    float* MN  = pool + OFF_MN;    // ir,r
    float* HT  = pool + OFF_HT;
    float* WB0 = pool + OFF_WB;
    float* WB1 = pool + OFF_WB + 4096;
    float* WB2 = pool + OFF_WB + 8192;
    float* WB3 = pool + OFF_WB + 12288;

    __shared__ float adj0S[128], adj1S[128], eaS[128], WpS[64];
    __shared__ float yS2[256];
    __shared__ int selfRows[128];
    __shared__ int selfCnt;

    if (tid == 0) selfCnt = 0;
    __syncthreads();

    float4 pw[2], pw2[2];
    unsigned af[8][4];
    float acc[4][4];

    // ================= preA: stage S0/S1 weights + metadata + HT ==============
    wload2(Wn1 + 128 * 64, 64, tid, pw);            // Wn1[0] rows 128..191
    wload2(Wn1 + 16384 + 128 * 64, 64, tid, pw2);   // Wn1[1] rows 128..191

    const int qb = __ldg(&qt[b]);
    if (tid < 128) {
        const int row = tid;
        const int c = c0 + row;
        const float m = __ldg(&one_hot[(size_t)qb * 1024 + c]);
        adj0S[row] = g_adj[c];
        adj1S[row] = g_adj[1024 + c];
        eaS[row]   = __ldg(&ea_w[c]);
        if (m > 0.5f) { int p = atomicAdd(&selfCnt, 1); selfRows[p] = row; }
    }
    if (tid < 64) WpS[tid] = __ldg(&Wpv[tid]);

    for (int i = tid; i < 2048; i += NT) {
        const int row = i & 127;
        const int f4  = i >> 7;
        const float4 v = __ldg(reinterpret_cast<const float4*>(
                               &ht[((size_t)b * 1024 + c0 + row) * 64]) + f4);
        const int f = f4 * 4;
        HT[(f + 0) * ROWP + row] = v.x;
        HT[(f + 1) * ROWP + row] = v.y;
        HT[(f + 2) * ROWP + row] = v.z;
        HT[(f + 3) * ROWP + row] = v.w;
    }
    wstore2(pw, WB0, tid);
    wstore2(pw2, WB1, tid);
    __syncthreads();                                            // B1

    const float w = clipf(__ldg(&nwp[0]), 0.1f, 0.9f);

    // ================= Sec1: clip(HT) @ Wn1[0/1] -> H1A,H1B ===================
    wload2(Wn2, 64, tid, pw);                       // -> B2
    load_af_clip(HT, m0, t4, g8, af);
    zacc(acc);
    gemm_frag(af, WB0, wn, lane, acc);
    {
        const float* P1k = g_P1;
#pragma unroll
        for (int c4 = 0; c4 < 4; ++c4) {
            const int j0 = (wn * 4 + c4) * 8 + 2 * t4;
            const float2 pa = *reinterpret_cast<const float2*>(&P1k[(size_t)(c0 + rA) * 64 + j0]);
            const float2 pb = *reinterpret_cast<const float2*>(&P1k[(size_t)(c0 + rB) * 64 + j0]);
            H1A[j0 * ROWP + rA]       = fmaxf(acc[c4][0] + pa.x, 0.0f);
            H1A[(j0 + 1) * ROWP + rA] = fmaxf(acc[c4][1] + pa.y, 0.0f);
            H1A[j0 * ROWP + rB]       = fmaxf(acc[c4][2] + pb.x, 0.0f);
            H1A[(j0 + 1) * ROWP + rB] = fmaxf(acc[c4][3] + pb.y, 0.0f);
        }
    }
    wstore2(pw, WB2, tid);
    wload2(Wn2 + 4096, 64, tid, pw);                // -> B3
    zacc(acc);
    gemm_frag(af, WB1, wn, lane, acc);
    {
        const float* P1k = g_P1 + (size_t)1024 * 64;
#pragma unroll
        for (int c4 = 0; c4 < 4; ++c4) {
            const int j0 = (wn * 4 + c4) * 8 + 2 * t4;
            const float2 pa = *reinterpret_cast<const float2*>(&P1k[(size_t)(c0 + rA) * 64 + j0]);
            const float2 pb = *reinterpret_cast<const float2*>(&P1k[(size_t)(c0 + rB) * 64 + j0]);
            H1B[j0 * ROWP + rA]       = fmaxf(acc[c4][0] + pa.x, 0.0f);
            H1B[(j0 + 1) * ROWP + rA] = fmaxf(acc[c4][1] + pa.y, 0.0f);
            H1B[j0 * ROWP + rB]       = fmaxf(acc[c4][2] + pb.x, 0.0f);
            H1B[(j0 + 1) * ROWP + rB] = fmaxf(acc[c4][3] + pb.y, 0.0f);
        }
    }
    wstore2(pw, WB3, tid);
    __syncthreads();                                            // B2

    // ================= Sec2: H1A/H1B @ Wn2[0/1] -> MN =========================
    wload2(We, 64, tid, pw);                        // -> B0
    load_af(H1A, m0, t4, g8, af);
    zacc(acc);
    gemm_frag(af, WB2, wn, lane, acc);
#pragma unroll
    for (int c4 = 0; c4 < 4; ++c4) {
        const int j0 = (wn * 4 + c4) * 8 + 2 * t4;
#pragma unroll
        for (int h = 0; h < 2; ++h) {
            const int j = j0 + h;
            const float bb = __ldg(&bn2[j]);
            const float nbA = fminf(fmaxf(acc[c4][h] + bb, 0.0f), 5.0f);
            const float nbB = fminf(fmaxf(acc[c4][2 + h] + bb, 0.0f), 5.0f);
            MN[j * ROWP + rA] = clipf(adj0S[rA] * nbA, -5.0f, 5.0f);
            MN[j * ROWP + rB] = clipf(adj0S[rB] * nbB, -5.0f, 5.0f);
        }
    }
    wstore2(pw, WB0, tid);
    wload2(Wa, 64, tid, pw);                        // -> B1
    load_af(H1B, m0, t4, g8, af);
    zacc(acc);
    gemm_frag(af, WB3, wn, lane, acc);
#pragma unroll
    for (int c4 = 0; c4 < 4; ++c4) {
        const int j0 = (wn * 4 + c4) * 8 + 2 * t4;
#pragma unroll
        for (int h = 0; h < 2; ++h) {
            const int j = j0 + h;
            const float bb = __ldg(&bn2[64 + j]);
            const float nbA = fminf(fmaxf(acc[c4][h] + bb, 0.0f), 5.0f);
            const float nbB = fminf(fmaxf(acc[c4][2 + h] + bb, 0.0f), 5.0f);
            float* mA = &MN[j * ROWP + rA];
            float* mB = &MN[j * ROWP + rB];
            *mA = clipf(w * (*mA) + (1.0f - w) * adj1S[rA] * nbA, -5.0f, 5.0f);
            *mB = clipf(w * (*mB) + (1.0f - w) * adj1S[rB] * nbB, -5.0f, 5.0f);
        }
    }
    wstore2(pw, WB1, tid);
    __syncthreads();                                            // B3

    // ================= Phase C: sparse self-MLP fixup (conditional) ===========
    if (selfCnt > 0) {
        float* selfH1 = H1B;   // dead after Sec2's af load
        const int nSelf = selfCnt;
        for (int s = warpId; s < nSelf; s += 16) {
            const int row = selfRows[s];
            const int c = c0 + row;
            float a1 = __ldg(&bs1[lane]);
            float a2 = __ldg(&bs1[lane + 32]);
#pragma unroll 4
            for (int i = 0; i < 64; ++i) {
                const float xi = HT[i * ROWP + row];
                a1 = fmaf(xi, __ldg(&Ws1[i * 64 + lane]), a1);
                a2 = fmaf(xi, __ldg(&Ws1[i * 64 + lane + 32]), a2);
            }
#pragma unroll 4
            for (int i = 0; i < 64; ++i) {
                const float xi = __ldg(&kcE[(size_t)c * 64 + i]);
                a1 = fmaf(xi, __ldg(&Ws1[(64 + i) * 64 + lane]), a1);
                a2 = fmaf(xi, __ldg(&Ws1[(64 + i) * 64 + lane + 32]), a2);
            }
            selfH1[warpId * 64 + lane]      = fmaxf(a1, 0.0f);
            selfH1[warpId * 64 + lane + 32] = fmaxf(a2, 0.0f);
            __syncwarp();
            float o1 = __ldg(&bs2[lane]);
            float o2 = __ldg(&bs2[lane + 32]);
#pragma unroll 4
            for (int i = 0; i < 64; ++i) {
                const float h = selfH1[warpId * 64 + i];
                o1 = fmaf(h, __ldg(&Ws2[i * 64 + lane]), o1);
                o2 = fmaf(h, __ldg(&Ws2[i * 64 + lane + 32]), o2);
            }
            MN[lane * ROWP + row]        = fminf(fmaxf(o1, 0.0f), 10.0f);
            MN[(lane + 32) * ROWP + row] = fminf(fmaxf(o2, 0.0f), 10.0f);
            __syncwarp();
        }
        __syncthreads();                                        // B3b (cond)
    }

    // ================= Sec3: MN @ We -> SIG(H1A); MN @ Wa -> RES(H1B) =========
    wload2(W_ih, 192, tid, pw);                     // gi0 -> B2
    load_af(MN, m0, t4, g8, af);
    zacc(acc);
    gemm_frag(af, WB0, wn, lane, acc);
#pragma unroll
    for (int c4 = 0; c4 < 4; ++c4) {
        const int j0 = (wn * 4 + c4) * 8 + 2 * t4;
#pragma unroll
        for (int h = 0; h < 2; ++h) {
            const int j = j0 + h;
            const float bb = __ldg(&be[j]);
            H1A[j * ROWP + rA] = sigf(acc[c4][h] + bb);
            H1A[j * ROWP + rB] = sigf(acc[c4][2 + h] + bb);
        }
    }
    wstore2(pw, WB2, tid);
    wload2(W_ih + 64, 192, tid, pw);                // gi1 -> B3
    zacc(acc);
    gemm_frag(af, WB1, wn, lane, acc);
#pragma unroll
    for (int c4 = 0; c4 < 4; ++c4) {
        const int j0 = (wn * 4 + c4) * 8 + 2 * t4;
#pragma unroll
        for (int h = 0; h < 2; ++h) {
            const int j = j0 + h;
            const float bb = __ldg(&ba[j]);
            {
                const float mn = MN[j * ROWP + rA];
                const float g  = eaS[rA];
                H1B[j * ROWP + rA] = mn - g * H1A[j * ROWP + rA] * mn + g * tanhf(acc[c4][h] + bb);
            }
            {
                const float mn = MN[j * ROWP + rB];
                const float g  = eaS[rB];
                H1B[j * ROWP + rB] = mn - g * H1A[j * ROWP + rB] * mn + g * tanhf(acc[c4][2 + h] + bb);
            }
        }
    }
    wstore2(pw, WB3, tid);
    __syncthreads();                                            // B4

    // ================= Sec4: RES @ W_ih[0,1] -> ir(MN), iz(H1A) ===============
    wload2(W_ih + 128, 192, tid, pw);               // gi2 -> B0
    load_af(H1B, m0, t4, g8, af);                   // af(RES), kept through Sec5
    zacc(acc);
    gemm_frag(af, WB2, wn, lane, acc);
#pragma unroll
    for (int c4 = 0; c4 < 4; ++c4) {
        const int j0 = (wn * 4 + c4) * 8 + 2 * t4;
#pragma unroll
        for (int h = 0; h < 2; ++h) {
            const int j = j0 + h;
            const float bb = __ldg(&b_ih[j]);
            MN[j * ROWP + rA] = acc[c4][h] + bb;
            MN[j * ROWP + rB] = acc[c4][2 + h] + bb;
        }
    }
    wstore2(pw, WB0, tid);
    wload2(W_hh, 192, tid, pw);                     // gh0 -> B1
    zacc(acc);
    gemm_frag(af, WB3, wn, lane, acc);
#pragma unroll
    for (int c4 = 0; c4 < 4; ++c4) {
        const int j0 = (wn * 4 + c4) * 8 + 2 * t4;
#pragma unroll
        for (int h = 0; h < 2; ++h) {
            const int j = j0 + h;
            const float bb = __ldg(&b_ih[64 + j]);
            H1A[j * ROWP + rA] = acc[c4][h] + bb;
            H1A[j * ROWP + rB] = acc[c4][2 + h] + bb;
        }
    }
    wstore2(pw, WB1, tid);
    __syncthreads();                                            // B5

    // ================= Sec5: gi2 -> in_(H1B); gh0 -> r(MN) ====================
    wload2(W_hh + 64, 192, tid, pw);                // gh1 -> B2
    zacc(acc);
    gemm_frag(af, WB0, wn, lane, acc);              // af(RES) still in regs
#pragma unroll
    for (int c4 = 0; c4 < 4; ++c4) {
        const int j0 = (wn * 4 + c4) * 8 + 2 * t4;
#pragma unroll
        for (int h = 0; h < 2; ++h) {
            const int j = j0 + h;
            const float bb = __ldg(&b_ih[128 + j]);
            H1B[j * ROWP + rA] = acc[c4][h] + bb;   // in_ (RES consumed to regs)
            H1B[j * ROWP + rB] = acc[c4][2 + h] + bb;
        }
    }
    wstore2(pw, WB2, tid);
    wload2(W_hh + 128, 192, tid, pw);               // gh2 -> B3
    load_af(HT, m0, t4, g8, af);                    // af(HT), kept through Sec6
    zacc(acc);
    gemm_frag(af, WB1, wn, lane, acc);
#pragma unroll
    for (int c4 = 0; c4 < 4; ++c4) {
        const int j0 = (wn * 4 + c4) * 8 + 2 * t4;
#pragma unroll
        for (int h = 0; h < 2; ++h) {
            const int j = j0 + h;
            const float bb = __ldg(&b_hh[j]);
            float* pA = &MN[j * ROWP + rA];
            float* pB = &MN[j * ROWP + rB];
            *pA = sigf(*pA + acc[c4][h] + bb);      // r
            *pB = sigf(*pB + acc[c4][2 + h] + bb);
        }
    }
    wstore2(pw, WB3, tid);
    __syncthreads();                                            // B6

    // ================= Sec6: gh1 -> z(H1A); gh2 -> final ======================
    zacc(acc);
    gemm_frag(af, WB2, wn, lane, acc);
#pragma unroll
    for (int c4 = 0; c4 < 4; ++c4) {
        const int j0 = (wn * 4 + c4) * 8 + 2 * t4;
#pragma unroll
        for (int h = 0; h < 2; ++h) {
            const int j = j0 + h;
            const float bb = __ldg(&b_hh[64 + j]);
            float* pA = &H1A[j * ROWP + rA];
            float* pB = &H1A[j * ROWP + rB];
            *pA = sigf(*pA + acc[c4][h] + bb);      // z
            *pB = sigf(*pB + acc[c4][2 + h] + bb);
        }
    }
    zacc(acc);
    gemm_frag(af, WB3, wn, lane, acc);
    {
        float ypA = 0.0f, ypB = 0.0f;
#pragma unroll
        for (int c4 = 0; c4 < 4; ++c4) {
            const int j0 = (wn * 4 + c4) * 8 + 2 * t4;
#pragma unroll
            for (int h = 0; h < 2; ++h) {
                const int j = j0 + h;
                const float bb = __ldg(&b_hh[128 + j]);
                const float wp = WpS[j];
                {
                    const float r   = MN[j * ROWP + rA];
                    const float z   = H1A[j * ROWP + rA];
                    const float in_ = H1B[j * ROWP + rA];
                    const float n   = tanhf(in_ + r * (acc[c4][h] + bb));
                    const float hv  = HT[j * ROWP + rA];
                    ypA += ((1.0f - z) * n + z * hv) * wp;
                }
                {
                    const float r   = MN[j * ROWP + rB];
                    const float z   = H1A[j * ROWP + rB];
                    const float in_ = H1B[j * ROWP + rB];
                    const float n   = tanhf(in_ + r * (acc[c4][2 + h] + bb));
                    const float hv  = HT[j * ROWP + rB];
                    ypB += ((1.0f - z) * n + z * hv) * wp;
                }
            }
        }
        ypA += __shfl_xor_sync(0xffffffffu, ypA, 1);
        ypA += __shfl_xor_sync(0xffffffffu, ypA, 2);
        ypB += __shfl_xor_sync(0xffffffffu, ypB, 1);
        ypB += __shfl_xor_sync(0xffffffffu, ypB, 2);
        if (t4 == 0) {
            yS2[wn * 128 + rA] = ypA;
            yS2[wn * 128 + rB] = ypB;
        }
    }
    __syncthreads();                                            // B7

    if (tid < 128) {
        out[(size_t)b * 1024 + c0 + tid] =
            sigf(yS2[tid] + yS2[128 + tid] + __ldg(&bp[0]));
    }
}

// ---------------------------------------------------------------------------
// Launcher
// ---------------------------------------------------------------------------
extern "C" void kernel_launch(void* const* d_in, const int* in_sizes, int n_in,
                              void* d_out, int out_size)
{
    const int*   qt     = (const int*)  d_in[1];
    const float* ht     = (const float*)d_in[2];
    const float* oh     = (const float*)d_in[3];
    const float* kcE    = (const float*)d_in[4];
    const float* graphs = (const float*)d_in[5];
    const float* nw     = (const float*)d_in[6];
    const float* Ws1    = (const float*)d_in[7];
    const float* bs1    = (const float*)d_in[8];
    const float* Ws2    = (const float*)d_in[9];
    const float* bs2    = (const float*)d_in[10];
    const float* Wn1    = (const float*)d_in[11];
    const float* bn1    = (const float*)d_in[12];
    const float* Wn2    = (const float*)d_in[13];
    const float* bn2    = (const float*)d_in[14];
    const float* ea     = (const float*)d_in[15];
    const float* We     = (const float*)d_in[16];
    const float* be     = (const float*)d_in[17];
    const float* Wa     = (const float*)d_in[18];
    const float* ba     = (const float*)d_in[19];
    const float* Wih    = (const float*)d_in[20];
    const float* bih    = (const float*)d_in[21];
    const float* Whh    = (const float*)d_in[22];
    const float* bhh    = (const float*)d_in[23];
    const float* Wp     = (const float*)d_in[24];
    const float* bp     = (const float*)d_in[25];
    float* out = (float*)d_out;

    adj_kernel<<<dim3(2, 8), 128>>>(qt, oh, graphs);
    p1_kernel<<<dim3(256, 2), 256>>>(kcE, Wn1, bn1);

    const int smemBytes = SMEM_FLOATS * (int)sizeof(float); // 204800
    cudaFuncSetAttribute(main_kernel,
                         cudaFuncAttributeMaxDynamicSharedMemorySize, smemBytes);

    dim3 grid(8, 256);
    main_kernel<<<grid, NT, smemBytes>>>(qt, ht, oh, kcE, nw,
                                         Ws1, bs1, Ws2, bs2,
                                         Wn1, bn1, Wn2, bn2,
                                         ea, We, be, Wa, ba,
                                         Wih, bih, Whh, bhh, Wp, bp, out);
}

// round 16
// speedup vs baseline: 1.5418x; 1.2624x over previous
#include <cuda_runtime.h>
#include <cstdint>

#define NT 512
#define ROWP 136
#define SEG  8704          // 64 * ROWP

// Dynamic pool offsets (floats)
#define OFF_U    0         // U (B) / GB cols 0-63 (E)
#define OFF_H1A  8704      // H1a (B) / SIG (D) / GB 64-127 (E)
#define OFF_H1B  17408     // H1b (B) / selfH1 scratch (C) / GB 128-191 (E)
#define OFF_MN   26112     // MN (B..D) / RES (D..E, in place)
#define OFF_HT   34816     // raw ht (persistent)
#define OFF_WF0  43520     // weight staging buffer 0 (4096)
#define OFF_WF1  47616     // weight staging buffer 1 (4096)
#define SMEM_FLOATS 51712  // 206848 bytes dynamic

__device__ float g_adj[2048];
__device__ float g_P1[2 * 1024 * 64];

static __device__ __forceinline__ float clipf(float x, float lo, float hi) {
    return fminf(fmaxf(x, lo), hi);
}
static __device__ __forceinline__ float ex2f(float x) {
    float r; asm("ex2.approx.ftz.f32 %0, %1;" : "=f"(r) : "f"(x)); return r;
}
static __device__ __forceinline__ float rcpf(float x) {
    float r; asm("rcp.approx.ftz.f32 %0, %1;" : "=f"(r) : "f"(x)); return r;
}
// sigmoid(x) = 1 / (1 + 2^(-x*log2e))
static __device__ __forceinline__ float sigf(float x) {
    return rcpf(1.0f + ex2f(-1.4426950408889634f * x));
}
// tanh(x) = 1 - 2 / (1 + 2^(2x*log2e)); saturates correctly at +/-inf
static __device__ __forceinline__ float tanhf_fast(float x) {
    return fmaf(-2.0f, rcpf(1.0f + ex2f(2.8853900817779268f * x)), 1.0f);
}
static __device__ __forceinline__ unsigned f2tf(float x) {
    unsigned r;
    asm("cvt.rna.tf32.f32 %0, %1;" : "=r"(r) : "f"(x));
    return r;
}
static __device__ __forceinline__ void mma_tf32(float d[4],
                                                unsigned a0, unsigned a1,
                                                unsigned a2, unsigned a3,
                                                unsigned b0, unsigned b1) {
    asm volatile(
        "mma.sync.aligned.m16n8k8.row.col.f32.tf32.tf32.f32 "
        "{%0,%1,%2,%3}, {%4,%5,%6,%7}, {%8,%9}, {%0,%1,%2,%3};"
        : "+f"(d[0]), "+f"(d[1]), "+f"(d[2]), "+f"(d[3])
        : "r"(a0), "r"(a1), "r"(a2), "r"(a3), "r"(b0), "r"(b1));
}

// ---------------------------------------------------------------------------
// Merged prelude: blocks 0..511 compute P1; blocks 512..519 compute adj.
// P1[k][c][j] = bn1[k][j] + sum_e clip(kcE[c][e],±5) * Wn1[k][192+e][j]
// adj[k][d]   = clip( sum_c a0[c]*graphs[k,c,d] / max(sum(a0),1), -5, 5 )
// ---------------------------------------------------------------------------
__global__ void pre_kernel(const int* __restrict__ qt,
                           const float* __restrict__ one_hot,
                           const float* __restrict__ graphs,
                           const float* __restrict__ kcE,
                           const float* __restrict__ Wn1,
                           const float* __restrict__ bn1)
{
    const int bid = blockIdx.x;
    const int tid = threadIdx.x;
    if (bid < 512) {
        __shared__ float kcS[4][64];
        const int k  = bid >> 8;
        const int cl = tid >> 6;
        const int j  = tid & 63;
        const int c  = (bid & 255) * 4 + cl;
        kcS[cl][j] = clipf(__ldg(&kcE[c * 64 + j]), -5.0f, 5.0f);
        __syncthreads();
        float s = __ldg(&bn1[k * 64 + j]);
#pragma unroll 4
        for (int e = 0; e < 64; ++e)
            s = fmaf(kcS[cl][e],
                     __ldg(&Wn1[(size_t)k * 16384 + (size_t)(192 + e) * 64 + j]), s);
        g_P1[((size_t)k * 1024 + c) * 64 + j] = s;
    } else {
        __shared__ int nzIdx[1024];
        __shared__ int nzCnt;
        const int bid2 = bid - 512;          // 0..7
        const int k = bid2 & 1;
        const int d = (bid2 >> 1) * 256 + tid;
        if (tid == 0) nzCnt = 0;
        __syncthreads();
        const int q0 = __ldg(&qt[0]);
        for (int c = tid; c < 1024; c += 256) {
            if (__ldg(&one_hot[(size_t)q0 * 1024 + c]) > 0.5f) {
                int p = atomicAdd(&nzCnt, 1);
                nzIdx[p] = c;
            }
        }
        __syncthreads();
        const int cnt = nzCnt;
        const float denom = fmaxf((float)cnt, 1.0f);
        float s = 0.0f;
        for (int t = 0; t < cnt; ++t)
            s += __ldg(&graphs[((size_t)k * 1024 + (size_t)nzIdx[t]) * 1024 + d]);
        g_adj[k * 1024 + d] = clipf(s / denom, -5.0f, 5.0f);
    }
}

// ---------------------------------------------------------------------------
// Weight prefetch (regs) / store (frag order, tf32)
// ---------------------------------------------------------------------------
static __device__ __forceinline__ void wload(const float* __restrict__ g,
                                             int pitch, int tid, float pw[8])
{
#pragma unroll
    for (int q = 0; q < 8; ++q) {
        const int i = tid + q * NT;
        const int k = i >> 6, j = i & 63;
        pw[q] = __ldg(&g[k * pitch + j]);
    }
}
static __device__ __forceinline__ void wstore(const float pw[8],
                                              float* __restrict__ Wf, int tid)
{
#pragma unroll
    for (int q = 0; q < 8; ++q) {
        const int i = tid + q * NT;
        const int k = i >> 6, j = i & 63;
        const int kc = k >> 3, kk = k & 7;
        const int h = kk >> 2, t = kk & 3;
        const int nc = j >> 3, gg = j & 7;
        Wf[(kc * 8 + nc) * 64 + (gg * 4 + t) * 2 + h] = __uint_as_float(f2tf(pw[q]));
    }
}

// A fragments: 16 rows (m0..m0+15) x K=64, converted once, reused.
static __device__ __forceinline__ void load_af(const float* __restrict__ A,
                                               int m0, int t4, int g8,
                                               unsigned af[8][4])
{
    const float* Ab = A + m0 + g8;
#pragma unroll
    for (int kc = 0; kc < 8; ++kc) {
        const float* Ak = Ab + (kc * 8 + t4) * ROWP;
        af[kc][0] = f2tf(Ak[0]);
        af[kc][1] = f2tf(Ak[8]);
        af[kc][2] = f2tf(Ak[4 * ROWP]);
        af[kc][3] = f2tf(Ak[4 * ROWP + 8]);
    }
}
static __device__ __forceinline__ void gemm_frag(const unsigned af[8][4],
                                                 const float* __restrict__ Wf,
                                                 int wn, int lane, float acc[4][4])
{
#pragma unroll
    for (int kc = 0; kc < 8; ++kc) {
#pragma unroll
        for (int c4 = 0; c4 < 4; ++c4) {
            const float2 b = *reinterpret_cast<const float2*>(
                Wf + (kc * 8 + wn * 4 + c4) * 64 + lane * 2);
            mma_tf32(acc[c4], af[kc][0], af[kc][1], af[kc][2], af[kc][3],
                     __float_as_uint(b.x), __float_as_uint(b.y));
        }
    }
}
static __device__ __forceinline__ void zacc(float acc[4][4]) {
#pragma unroll
    for (int i = 0; i < 4; ++i)
#pragma unroll
        for (int j = 0; j < 4; ++j) acc[i][j] = 0.0f;
}

// ---------------------------------------------------------------------------
// Main fused kernel
// ---------------------------------------------------------------------------
extern __shared__ float dynsmem[];

__global__ void __launch_bounds__(NT, 1)
main_kernel(const int*   __restrict__ qt,
            const float* __restrict__ ht,
            const float* __restrict__ one_hot,
            const float* __restrict__ kcE,
            const float* __restrict__ nwp,
            const float* __restrict__ Ws1, const float* __restrict__ bs1,
            const float* __restrict__ Ws2, const float* __restrict__ bs2,
            const float* __restrict__ Wn1, const float* __restrict__ bn1,
            const float* __restrict__ Wn2, const float* __restrict__ bn2,
            const float* __restrict__ ea_w,
            const float* __restrict__ We,  const float* __restrict__ be,
            const float* __restrict__ Wa,  const float* __restrict__ ba,
            const float* __restrict__ W_ih, const float* __restrict__ b_ih,
            const float* __restrict__ W_hh, const float* __restrict__ b_hh,
            const float* __restrict__ Wpv, const float* __restrict__ bp,
            float* __restrict__ out)
{
    const int tid  = threadIdx.x;
    const int lane = tid & 31;
    const int warpId = tid >> 5;
    const int wm = warpId & 7;
    const int wn = warpId >> 3;
    const int m0 = wm * 16;
    const int t4 = lane & 3;
    const int g8 = lane >> 2;
    const int rA = m0 + g8;
    const int rB = rA + 8;
    const int c0 = blockIdx.x * 128;
    const int b  = blockIdx.y;

    float* pool = dynsmem;
    float* U   = pool + OFF_U;
    float* H1A = pool + OFF_H1A;   // SIG in D
    float* H1B = pool + OFF_H1B;   // selfH1 scratch in C
    float* MN  = pool + OFF_MN;    // RES in D..E
    float* HT  = pool + OFF_HT;
    float* GB  = pool + OFF_U;     // 192 x ROWP in phase E
    float* Wf0 = pool + OFF_WF0;
    float* Wf1 = pool + OFF_WF1;

    __shared__ float adj0S[128], adj1S[128], eaS[128], WpS[64];
    __shared__ float yS2[256];
    __shared__ int selfRows[128];
    __shared__ int selfCnt;

    if (tid == 0) selfCnt = 0;
    __syncthreads();

    float pw[8];
    unsigned af[8][4];
    float acc[4][4];

    // ---------------- Phase A: prefetch S0 weights + metadata + HT/U ----------
    wload(Wn1 + 128 * 64, 64, tid, pw);            // S0 = Wn1[0] rows 128..191

    const int qb = __ldg(&qt[b]);
    if (tid < 128) {
        const int row = tid;
        const int c = c0 + row;
        const float m = __ldg(&one_hot[(size_t)qb * 1024 + c]);
        adj0S[row] = g_adj[c];
        adj1S[row] = g_adj[1024 + c];
        eaS[row]   = __ldg(&ea_w[c]);
        if (m > 0.5f) { int p = atomicAdd(&selfCnt, 1); selfRows[p] = row; }
    }
    if (tid < 64) WpS[tid] = __ldg(&Wpv[tid]);

    for (int i = tid; i < 2048; i += NT) {
        const int row = i & 127;
        const int f4  = i >> 7;
        const float4 v = __ldg(reinterpret_cast<const float4*>(
                               &ht[((size_t)b * 1024 + c0 + row) * 64]) + f4);
        const int f = f4 * 4;
        HT[(f + 0) * ROWP + row] = v.x;
        HT[(f + 1) * ROWP + row] = v.y;
        HT[(f + 2) * ROWP + row] = v.z;
        HT[(f + 3) * ROWP + row] = v.w;
        U[(f + 0) * ROWP + row] = clipf(v.x, -5.0f, 5.0f);
        U[(f + 1) * ROWP + row] = clipf(v.y, -5.0f, 5.0f);
        U[(f + 2) * ROWP + row] = clipf(v.z, -5.0f, 5.0f);
        U[(f + 3) * ROWP + row] = clipf(v.w, -5.0f, 5.0f);
    }
    wstore(pw, Wf0, tid);
    __syncthreads();

    const float w = clipf(__ldg(&nwp[0]), 0.1f, 0.9f);

    // ---------------- S0: U @ Wn1[0] -> H1A -----------------------------------
    wload(Wn1 + 16384 + 128 * 64, 64, tid, pw);    // S1 = Wn1[1]
    load_af(U, m0, t4, g8, af);
    zacc(acc);
    gemm_frag(af, Wf0, wn, lane, acc);
    wstore(pw, Wf1, tid);
    {
        const float* P1k = g_P1;
#pragma unroll
        for (int c4 = 0; c4 < 4; ++c4) {
            const int j0 = (wn * 4 + c4) * 8 + 2 * t4;
            const float2 pa = *reinterpret_cast<const float2*>(&P1k[(size_t)(c0 + rA) * 64 + j0]);
            const float2 pb = *reinterpret_cast<const float2*>(&P1k[(size_t)(c0 + rB) * 64 + j0]);
            H1A[j0 * ROWP + rA]       = fmaxf(acc[c4][0] + pa.x, 0.0f);
            H1A[(j0 + 1) * ROWP + rA] = fmaxf(acc[c4][1] + pa.y, 0.0f);
            H1A[j0 * ROWP + rB]       = fmaxf(acc[c4][2] + pb.x, 0.0f);
            H1A[(j0 + 1) * ROWP + rB] = fmaxf(acc[c4][3] + pb.y, 0.0f);
        }
    }
    __syncthreads();

    // ---------------- S1: U @ Wn1[1] -> H1B (af reuse) ------------------------
    wload(Wn2, 64, tid, pw);                       // S2 = Wn2[0]
    zacc(acc);
    gemm_frag(af, Wf1, wn, lane, acc);
    wstore(pw, Wf0, tid);
    {
        const float* P1k = g_P1 + (size_t)1024 * 64;
#pragma unroll
        for (int c4 = 0; c4 < 4; ++c4) {
            const int j0 = (wn * 4 + c4) * 8 + 2 * t4;
            const float2 pa = *reinterpret_cast<const float2*>(&P1k[(size_t)(c0 + rA) * 64 + j0]);
            const float2 pb = *reinterpret_cast<const float2*>(&P1k[(size_t)(c0 + rB) * 64 + j0]);
            H1B[j0 * ROWP + rA]       = fmaxf(acc[c4][0] + pa.x, 0.0f);
            H1B[(j0 + 1) * ROWP + rA] = fmaxf(acc[c4][1] + pa.y, 0.0f);
            H1B[j0 * ROWP + rB]       = fmaxf(acc[c4][2] + pb.x, 0.0f);
            H1B[(j0 + 1) * ROWP + rB] = fmaxf(acc[c4][3] + pb.y, 0.0f);
        }
    }
    __syncthreads();

    // ---------------- S2: H1A @ Wn2[0] -> MN (k=0) ----------------------------
    wload(Wn2 + 4096, 64, tid, pw);                // S3 = Wn2[1]
    load_af(H1A, m0, t4, g8, af);
    zacc(acc);
    gemm_frag(af, Wf0, wn, lane, acc);
    wstore(pw, Wf1, tid);
#pragma unroll
    for (int c4 = 0; c4 < 4; ++c4) {
        const int j0 = (wn * 4 + c4) * 8 + 2 * t4;
#pragma unroll
        for (int h = 0; h < 2; ++h) {
            const int j = j0 + h;
            const float bb = __ldg(&bn2[j]);
            const float nbA = fminf(fmaxf(acc[c4][h] + bb, 0.0f), 5.0f);
            const float nbB = fminf(fmaxf(acc[c4][2 + h] + bb, 0.0f), 5.0f);
            MN[j * ROWP + rA] = clipf(adj0S[rA] * nbA, -5.0f, 5.0f);
            MN[j * ROWP + rB] = clipf(adj0S[rB] * nbB, -5.0f, 5.0f);
        }
    }
    __syncthreads();

    // ---------------- S3: H1B @ Wn2[1] -> MN combine --------------------------
    wload(We, 64, tid, pw);                        // S4 = We
    load_af(H1B, m0, t4, g8, af);
    zacc(acc);
    gemm_frag(af, Wf1, wn, lane, acc);
    wstore(pw, Wf0, tid);
#pragma unroll
    for (int c4 = 0; c4 < 4; ++c4) {
        const int j0 = (wn * 4 + c4) * 8 + 2 * t4;
#pragma unroll
        for (int h = 0; h < 2; ++h) {
            const int j = j0 + h;
            const float bb = __ldg(&bn2[64 + j]);
            const float nbA = fminf(fmaxf(acc[c4][h] + bb, 0.0f), 5.0f);
            const float nbB = fminf(fmaxf(acc[c4][2 + h] + bb, 0.0f), 5.0f);
            float* mA = &MN[j * ROWP + rA];
            float* mB = &MN[j * ROWP + rB];
            *mA = clipf(w * (*mA) + (1.0f - w) * adj1S[rA] * nbA, -5.0f, 5.0f);
            *mB = clipf(w * (*mB) + (1.0f - w) * adj1S[rB] * nbB, -5.0f, 5.0f);
        }
    }
    __syncthreads();

    // ---------------- Phase C: sparse self-MLP fixup --------------------------
    {
        float* selfH1 = H1B;   // dead after S3's af load
        const int nSelf = selfCnt;
        for (int s = warpId; s < nSelf; s += 16) {
            const int row = selfRows[s];
            const int c = c0 + row;
            float a1 = __ldg(&bs1[lane]);
            float a2 = __ldg(&bs1[lane + 32]);
#pragma unroll 4
            for (int i = 0; i < 64; ++i) {
                const float xi = HT[i * ROWP + row];
                a1 = fmaf(xi, __ldg(&Ws1[i * 64 + lane]), a1);
                a2 = fmaf(xi, __ldg(&Ws1[i * 64 + lane + 32]), a2);
            }
#pragma unroll 4
            for (int i = 0; i < 64; ++i) {
                const float xi = __ldg(&kcE[(size_t)c * 64 + i]);
                a1 = fmaf(xi, __ldg(&Ws1[(64 + i) * 64 + lane]), a1);
                a2 = fmaf(xi, __ldg(&Ws1[(64 + i) * 64 + lane + 32]), a2);
            }
            selfH1[warpId * 64 + lane]      = fmaxf(a1, 0.0f);
            selfH1[warpId * 64 + lane + 32] = fmaxf(a2, 0.0f);
            __syncwarp();
            float o1 = __ldg(&bs2[lane]);
            float o2 = __ldg(&bs2[lane + 32]);
#pragma unroll 4
            for (int i = 0; i < 64; ++i) {
                const float h = selfH1[warpId * 64 + i];
                o1 = fmaf(h, __ldg(&Ws2[i * 64 + lane]), o1);
                o2 = fmaf(h, __ldg(&Ws2[i * 64 + lane + 32]), o2);
            }
            MN[lane * ROWP + row]        = fminf(fmaxf(o1, 0.0f), 10.0f);
            MN[(lane + 32) * ROWP + row] = fminf(fmaxf(o2, 0.0f), 10.0f);
            __syncwarp();
        }
    }
    __syncthreads();

    // ---------------- S4: MN @ We -> SIG --------------------------------------
    float* SIG = H1A;
    float* RES = MN;

    wload(Wa, 64, tid, pw);                        // S5 = Wa
    load_af(MN, m0, t4, g8, af);
    zacc(acc);
    gemm_frag(af, Wf0, wn, lane, acc);
    wstore(pw, Wf1, tid);
#pragma unroll
    for (int c4 = 0; c4 < 4; ++c4) {
        const int j0 = (wn * 4 + c4) * 8 + 2 * t4;
#pragma unroll
        for (int h = 0; h < 2; ++h) {
            const int j = j0 + h;
            const float bb = __ldg(&be[j]);
            SIG[j * ROWP + rA] = sigf(acc[c4][h] + bb);
            SIG[j * ROWP + rB] = sigf(acc[c4][2 + h] + bb);
        }
    }
    __syncthreads();

    // ---------------- S5: MN @ Wa -> RES (in place, af reuse) -----------------
    wload(W_hh, 192, tid, pw);                     // S6 = W_hh p0
    zacc(acc);
    gemm_frag(af, Wf1, wn, lane, acc);
    wstore(pw, Wf0, tid);
#pragma unroll
    for (int c4 = 0; c4 < 4; ++c4) {
        const int j0 = (wn * 4 + c4) * 8 + 2 * t4;
#pragma unroll
        for (int h = 0; h < 2; ++h) {
            const int j = j0 + h;
            const float bb = __ldg(&ba[j]);
            {
                const float mn = MN[j * ROWP + rA];
                const float g  = eaS[rA];
                RES[j * ROWP + rA] = mn - g * SIG[j * ROWP + rA] * mn + g * tanhf_fast(acc[c4][h] + bb);
            }
            {
                const float mn = MN[j * ROWP + rB];
                const float g  = eaS[rB];
                RES[j * ROWP + rB] = mn - g * SIG[j * ROWP + rB] * mn + g * tanhf_fast(acc[c4][2 + h] + bb);
            }
        }
    }
    __syncthreads();

    // ---------------- S6..S8: HT @ W_hh -> GB (af loaded once) ----------------
    load_af(HT, m0, t4, g8, af);
#pragma unroll 1
    for (int p = 0; p < 3; ++p) {
        // prefetch next stage weights
        if (p == 0)      wload(W_hh + 64, 192, tid, pw);   // S7
        else if (p == 1) wload(W_hh + 128, 192, tid, pw);  // S8
        else             wload(W_ih, 192, tid, pw);        // S9
        zacc(acc);
        gemm_frag(af, (p & 1) ? Wf1 : Wf0, wn, lane, acc);
        wstore(pw, (p & 1) ? Wf0 : Wf1, tid);
#pragma unroll
        for (int c4 = 0; c4 < 4; ++c4) {
            const int j0 = (wn * 4 + c4) * 8 + 2 * t4;
#pragma unroll
            for (int h = 0; h < 2; ++h) {
                const int j = p * 64 + j0 + h;
                const float bb = __ldg(&b_hh[j]);
                GB[j * ROWP + rA] = acc[c4][h] + bb;
                GB[j * ROWP + rB] = acc[c4][2 + h] + bb;
            }
        }
        __syncthreads();
    }

    // ---------------- S9..S10: RES @ W_ih -> gates (af loaded once) -----------
    load_af(RES, m0, t4, g8, af);
#pragma unroll 1
    for (int p = 0; p < 2; ++p) {
        if (p == 0) wload(W_ih + 64, 192, tid, pw);        // S10
        else        wload(W_ih + 128, 192, tid, pw);       // S11
        zacc(acc);
        gemm_frag(af, (p & 1) ? Wf0 : Wf1, wn, lane, acc); // S9 uses Wf1, S10 Wf0
        wstore(pw, (p & 1) ? Wf1 : Wf0, tid);
#pragma unroll
        for (int c4 = 0; c4 < 4; ++c4) {
            const int j0 = (wn * 4 + c4) * 8 + 2 * t4;
#pragma unroll
            for (int h = 0; h < 2; ++h) {
                const int j = p * 64 + j0 + h;
                const float bb = __ldg(&b_ih[j]);
                GB[j * ROWP + rA] = sigf(acc[c4][h] + bb + GB[j * ROWP + rA]);
                GB[j * ROWP + rB] = sigf(acc[c4][2 + h] + bb + GB[j * ROWP + rB]);
            }
        }
        __syncthreads();
    }

    // ---------------- S11: final gi pass + GRU + readout ----------------------
    zacc(acc);
    gemm_frag(af, Wf1, wn, lane, acc);
    {
        float ypA = 0.0f, ypB = 0.0f;
#pragma unroll
        for (int c4 = 0; c4 < 4; ++c4) {
            const int j0 = (wn * 4 + c4) * 8 + 2 * t4;
#pragma unroll
            for (int h = 0; h < 2; ++h) {
                const int j = j0 + h;
                const float bb = __ldg(&b_ih[128 + j]);
                const float wp = WpS[j];
                {
                    const float r  = GB[j * ROWP + rA];
                    const float z  = GB[(64 + j) * ROWP + rA];
                    const float hn = GB[(128 + j) * ROWP + rA];
                    const float n  = tanhf_fast(acc[c4][h] + bb + r * hn);
                    const float hv = HT[j * ROWP + rA];
                    ypA += ((1.0f - z) * n + z * hv) * wp;
                }
                {
                    const float r  = GB[j * ROWP + rB];
                    const float z  = GB[(64 + j) * ROWP + rB];
                    const float hn = GB[(128 + j) * ROWP + rB];
                    const float n  = tanhf_fast(acc[c4][2 + h] + bb + r * hn);
                    const float hv = HT[j * ROWP + rB];
                    ypB += ((1.0f - z) * n + z * hv) * wp;
                }
            }
        }
        ypA += __shfl_xor_sync(0xffffffffu, ypA, 1);
        ypA += __shfl_xor_sync(0xffffffffu, ypA, 2);
        ypB += __shfl_xor_sync(0xffffffffu, ypB, 1);
        ypB += __shfl_xor_sync(0xffffffffu, ypB, 2);
        if (t4 == 0) {
            yS2[wn * 128 + rA] = ypA;
            yS2[wn * 128 + rB] = ypB;
        }
    }
    __syncthreads();

    if (tid < 128) {
        out[(size_t)b * 1024 + c0 + tid] =
            sigf(yS2[tid] + yS2[128 + tid] + __ldg(&bp[0]));
    }
}

// ---------------------------------------------------------------------------
// Launcher
// ---------------------------------------------------------------------------
extern "C" void kernel_launch(void* const* d_in, const int* in_sizes, int n_in,
                              void* d_out, int out_size)
{
    const int*   qt     = (const int*)  d_in[1];
    const float* ht     = (const float*)d_in[2];
    const float* oh     = (const float*)d_in[3];
    const float* kcE    = (const float*)d_in[4];
    const float* graphs = (const float*)d_in[5];
    const float* nw     = (const float*)d_in[6];
    const float* Ws1    = (const float*)d_in[7];
    const float* bs1    = (const float*)d_in[8];
    const float* Ws2    = (const float*)d_in[9];
    const float* bs2    = (const float*)d_in[10];
    const float* Wn1    = (const float*)d_in[11];
    const float* bn1    = (const float*)d_in[12];
    const float* Wn2    = (const float*)d_in[13];
    const float* bn2    = (const float*)d_in[14];
    const float* ea     = (const float*)d_in[15];
    const float* We     = (const float*)d_in[16];
    const float* be     = (const float*)d_in[17];
    const float* Wa     = (const float*)d_in[18];
    const float* ba     = (const float*)d_in[19];
    const float* Wih    = (const float*)d_in[20];
    const float* bih    = (const float*)d_in[21];
    const float* Whh    = (const float*)d_in[22];
    const float* bhh    = (const float*)d_in[23];
    const float* Wp     = (const float*)d_in[24];
    const float* bp     = (const float*)d_in[25];
    float* out = (float*)d_out;

    pre_kernel<<<520, 256>>>(qt, oh, graphs, kcE, Wn1, bn1);

    const int smemBytes = SMEM_FLOATS * (int)sizeof(float); // 206848
    cudaFuncSetAttribute(main_kernel,
                         cudaFuncAttributeMaxDynamicSharedMemorySize, smemBytes);

    dim3 grid(8, 256);
    main_kernel<<<grid, NT, smemBytes>>>(qt, ht, oh, kcE, nw,
                                         Ws1, bs1, Ws2, bs2,
                                         Wn1, bn1, Wn2, bn2,
                                         ea, We, be, Wa, ba,
                                         Wih, bih, Whh, bhh, Wp, bp, out);
}